// round 10
// baseline (speedup 1.0000x reference)
#include <cuda_runtime.h>
#include <math.h>

#define S_LEN 512
#define B_SZ  64
#define HID   512
#define G3    1536
#define EMB_D 256
#define M_ROWS (S_LEN * B_SZ)   // 32768

typedef unsigned long long ull;

// ---------------- packed f32x2 helpers --------------------------------------
__device__ __forceinline__ ull pk2(float lo, float hi) {
    ull r; asm("mov.b64 %0, {%1,%2};" : "=l"(r) : "f"(lo), "f"(hi)); return r;
}
__device__ __forceinline__ ull dup2(float v) { return pk2(v, v); }
__device__ __forceinline__ void ffma2(ull& d, ull a, ull b) {
    asm("fma.rn.f32x2 %0, %1, %2, %0;" : "+l"(d) : "l"(a), "l"(b));
}
__device__ __forceinline__ ull add2(ull a, ull b) {
    ull r; asm("add.rn.f32x2 %0, %1, %2;" : "=l"(r) : "l"(a), "l"(b)); return r;
}
__device__ __forceinline__ float2 unpk2(ull v) {
    float2 f; asm("mov.b64 {%0,%1}, %2;" : "=f"(f.x), "=f"(f.y) : "l"(v)); return f;
}

// ---------------- scratch (static device globals; no allocation) ------------
__device__ float g_xg[(size_t)M_ROWS * G3];        // 192 MB
__device__ float g_ys[(size_t)M_ROWS * HID];       // 64 MB
__device__ unsigned int g_flags[4][32][32];         // one flag per 128B line

// ---------------- C[M,N] = A[M,K] @ W[N,K]^T + bias[N] ----------------------
// If x != nullptr, A-rows are gathered from the embedding table:
//   A[m][k] = (tok = x[b*512+s], m = s*64+b) ? emb[tok][k] : 0   (PAD tok==0)
__global__ void __launch_bounds__(256, 2) gemm_bias_kernel(
    const int* __restrict__ x, const float* __restrict__ emb,
    const float* __restrict__ A, const float* __restrict__ W,
    const float* __restrict__ bias, float* __restrict__ C,
    int M, int N, int K) {
    __shared__ float As[2][16][128];
    __shared__ float Bs[2][16][128];

    const int tid = threadIdx.x;
    const int n0 = blockIdx.x * 128;
    const int m0 = blockIdx.y * 128;
    const int tx = tid & 15, ty = tid >> 4;

    // each thread stages ONE A-row and ONE W-row (two k-quarters each)
    const int row = (tid * 2) >> 2;          // same for i=0,1
    const int kq0 = (tid * 2) & 3, kq1 = kq0 + 1;
    const float* Arow;
    bool azero = false;
    if (x) {
        int m = m0 + row;
        int s = m >> 6, b = m & 63;
        int tok = x[b * S_LEN + s];
        azero = (tok == 0);
        Arow = emb + (size_t)tok * EMB_D;
    } else {
        Arow = A + (size_t)(m0 + row) * K;
    }
    const float* Wrow = W + (size_t)(n0 + row) * K;

    ull acc2[4][8];
#pragma unroll
    for (int p = 0; p < 4; p++)
#pragma unroll
        for (int j = 0; j < 8; j++) acc2[p][j] = 0ULL;

    const int KT = K >> 4;
    const float4 FZ = make_float4(0.f, 0.f, 0.f, 0.f);

    // preload stage 0
    {
        float4 va0 = azero ? FZ : *(const float4*)(Arow + kq0 * 4);
        float4 va1 = azero ? FZ : *(const float4*)(Arow + kq1 * 4);
        float4 vb0 = *(const float4*)(Wrow + kq0 * 4);
        float4 vb1 = *(const float4*)(Wrow + kq1 * 4);
        As[0][kq0 * 4 + 0][row] = va0.x; As[0][kq0 * 4 + 1][row] = va0.y;
        As[0][kq0 * 4 + 2][row] = va0.z; As[0][kq0 * 4 + 3][row] = va0.w;
        As[0][kq1 * 4 + 0][row] = va1.x; As[0][kq1 * 4 + 1][row] = va1.y;
        As[0][kq1 * 4 + 2][row] = va1.z; As[0][kq1 * 4 + 3][row] = va1.w;
        Bs[0][kq0 * 4 + 0][row] = vb0.x; Bs[0][kq0 * 4 + 1][row] = vb0.y;
        Bs[0][kq0 * 4 + 2][row] = vb0.z; Bs[0][kq0 * 4 + 3][row] = vb0.w;
        Bs[0][kq1 * 4 + 0][row] = vb1.x; Bs[0][kq1 * 4 + 1][row] = vb1.y;
        Bs[0][kq1 * 4 + 2][row] = vb1.z; Bs[0][kq1 * 4 + 3][row] = vb1.w;
    }
    __syncthreads();

    for (int kt = 0; kt < KT; ++kt) {
        const int cur = kt & 1;
        float4 pa0, pa1, pb0, pb1;
        const bool pf = (kt + 1) < KT;
        if (pf) {
            int ko = (kt + 1) * 16;
            pa0 = azero ? FZ : *(const float4*)(Arow + ko + kq0 * 4);
            pa1 = azero ? FZ : *(const float4*)(Arow + ko + kq1 * 4);
            pb0 = *(const float4*)(Wrow + ko + kq0 * 4);
            pb1 = *(const float4*)(Wrow + ko + kq1 * 4);
        }
#pragma unroll
        for (int kk = 0; kk < 16; kk++) {
            ulonglong2 a01 = *(const ulonglong2*)&As[cur][kk][ty * 4];
            ulonglong2 a23 = *(const ulonglong2*)&As[cur][kk][64 + ty * 4];
            ull ap[4] = { a01.x, a01.y, a23.x, a23.y };
            float b[8];
            *(float4*)(b)     = *(const float4*)&Bs[cur][kk][tx * 4];
            *(float4*)(b + 4) = *(const float4*)&Bs[cur][kk][64 + tx * 4];
#pragma unroll
            for (int j = 0; j < 8; j++) {
                ull bd = dup2(b[j]);
#pragma unroll
                for (int p = 0; p < 4; p++) ffma2(acc2[p][j], ap[p], bd);
            }
        }
        if (pf) {
            const int nxt = cur ^ 1;
            As[nxt][kq0 * 4 + 0][row] = pa0.x; As[nxt][kq0 * 4 + 1][row] = pa0.y;
            As[nxt][kq0 * 4 + 2][row] = pa0.z; As[nxt][kq0 * 4 + 3][row] = pa0.w;
            As[nxt][kq1 * 4 + 0][row] = pa1.x; As[nxt][kq1 * 4 + 1][row] = pa1.y;
            As[nxt][kq1 * 4 + 2][row] = pa1.z; As[nxt][kq1 * 4 + 3][row] = pa1.w;
            Bs[nxt][kq0 * 4 + 0][row] = pb0.x; Bs[nxt][kq0 * 4 + 1][row] = pb0.y;
            Bs[nxt][kq0 * 4 + 2][row] = pb0.z; Bs[nxt][kq0 * 4 + 3][row] = pb0.w;
            Bs[nxt][kq1 * 4 + 0][row] = pb1.x; Bs[nxt][kq1 * 4 + 1][row] = pb1.y;
            Bs[nxt][kq1 * 4 + 2][row] = pb1.z; Bs[nxt][kq1 * 4 + 3][row] = pb1.w;
        }
        __syncthreads();
    }

    float4 bb0 = *(const float4*)&bias[n0 + tx * 4];
    float4 bb1 = *(const float4*)&bias[n0 + 64 + tx * 4];
#pragma unroll
    for (int p = 0; p < 4; p++) {
        float2 c[8];
#pragma unroll
        for (int j = 0; j < 8; j++) c[j] = unpk2(acc2[p][j]);
#pragma unroll
        for (int half = 0; half < 2; half++) {
            int i = 2 * p + half;
            int m = m0 + ((i < 4) ? (ty * 4 + i) : (64 + ty * 4 + i - 4));
            float e[8];
#pragma unroll
            for (int j = 0; j < 8; j++) e[j] = half ? c[j].y : c[j].x;
            float4 v0 = make_float4(e[0] + bb0.x, e[1] + bb0.y,
                                    e[2] + bb0.z, e[3] + bb0.w);
            float4 v1 = make_float4(e[4] + bb1.x, e[5] + bb1.y,
                                    e[6] + bb1.z, e[7] + bb1.w);
            *(float4*)(C + (size_t)m * N + n0 + tx * 4)      = v0;
            *(float4*)(C + (size_t)m * N + n0 + 64 + tx * 4) = v1;
        }
    }
}

// ---------------- GRU recurrence ---------------------------------------------
// 128 blocks = 4 batch groups (16 rows) x 32 dim groups (16 dims), 512 threads.
// Warp w stages+computes k in [32w, 32w+32): half-lanes 0-15 do k, 16-31 do k+16.
// h_old lives in gating-thread registers (no cross-warp hsh read).
// part: float4 (r,z,n,0) per (kg,row,dim), row stride 17 float4s.
#define WSH_STRIDE 48
#define HSH_STRIDE 17
#define PART_F4_RSTRIDE 17
#define GRU_SMEM_FLOATS (512 * WSH_STRIDE + 512 * HSH_STRIDE + 16 * 16 * PART_F4_RSTRIDE * 4)
#define GRU_SMEM_BYTES  (GRU_SMEM_FLOATS * 4)

__device__ __forceinline__ unsigned ld_acq(const unsigned* p) {
    unsigned v;
    asm volatile("ld.global.acquire.gpu.u32 %0, [%1];" : "=r"(v) : "l"(p) : "memory");
    return v;
}
__device__ __forceinline__ void st_rel(unsigned* p, unsigned v) {
    asm volatile("st.global.release.gpu.u32 [%0], %1;" :: "l"(p), "r"(v) : "memory");
}
__device__ __forceinline__ int hswz(int k) { return ((k >> 1) ^ (k >> 5)) & 15; }

__global__ void __launch_bounds__(512, 1) gru_kernel(
    const float* __restrict__ xg,    // [S][64][1536]
    const float* __restrict__ Whh,   // [1536][512]
    const float* __restrict__ bhh,   // [1536]
    float* __restrict__ ys)          // [S][64][512]
{
    extern __shared__ float sm[];
    float* Wsh  = sm;
    float* hsh  = Wsh + 512 * WSH_STRIDE;
    float* part = hsh + 512 * HSH_STRIDE;
    __shared__ unsigned sh_base;

    const int tid = threadIdx.x;
    const int bg  = blockIdx.x & 3;
    const int dg  = blockIdx.x >> 2;
    const int rowBase = bg * 16;
    const int dimBase = dg * 16;

    if (tid == 0) sh_base = *(volatile unsigned*)&g_flags[bg][dg][0];

    // load W_hh slice (48 gate cols) into smem, k-major
    for (int idx = tid; idx < 48 * 512; idx += 512) {
        int col = idx >> 9;       // 0..47  (col = dimLocal*3 + gate)
        int k   = idx & 511;
        int dl = col / 3, g = col % 3;
        int grow = g * 512 + dimBase + dl;
        Wsh[k * WSH_STRIDE + col] = Whh[(size_t)grow * 512 + k];
    }

    // gating role (tid < 256): one thread per (row, dim); h_old in a register
    const int myrow = (tid >> 4) & 15;
    const int mydl  = tid & 15;
    const int mydim = dimBase + mydl;
    float b_r = 0.f, b_z = 0.f, b_n = 0.f;
    float h_old = 0.f;
    if (tid < 256) {
        b_r = bhh[mydim]; b_z = bhh[512 + mydim]; b_n = bhh[1024 + mydim];
    }

    // compute role
    const int w    = tid >> 5;            // warp 0..15, k chunk [32w, 32w+32)
    const int lane = tid & 31;
    const int half = lane >> 4;           // 0: k, 1: k+16
    const int l    = lane & 15;
    const int rg   = l >> 2;              // row group: rows 4rg..4rg+3
    const int dgi  = l & 3;               // dim group: local dims 4dgi..4dgi+3
    const int rb   = rg * 4;
    const int k0   = w * 32;

    __syncthreads();
    const unsigned base = sh_base;

    for (int t = 0; t < S_LEN; ++t) {
        // xg prefetch for gating
        float xr = 0.f, xz = 0.f, xn = 0.f;
        if (tid < 256) {
            size_t xbase = ((size_t)t * 64 + rowBase + myrow) * G3 + mydim;
            xr = xg[xbase]; xz = xg[xbase + 512]; xn = xg[xbase + 1024];
        }

        // ---- warp-private h staging ----
        if (t == 0) {
            for (int idx = lane; idx < 32 * HSH_STRIDE; idx += 32)
                hsh[k0 * HSH_STRIDE + idx] = 0.f;
            __syncwarp();
        } else {
            const unsigned target = base + (unsigned)t;
            const float4* hsrc4 = (const float4*)(ys + ((size_t)(t - 1) * 64 + rowBase) * HID);
            float4 v[2][2];
#pragma unroll
            for (int j = 0; j < 2; j++) {
                const int c = 2 * w + j;   // producer chunk (16 dims = 16 k)
                const unsigned* fp = &g_flags[bg][c][0];
                while ((int)(ld_acq(fp) - target) < 0) { }
#pragma unroll
                for (int i = 0; i < 2; i++) {
                    int idx = i * 32 + lane;
                    int r = idx & 15, fq = idx >> 4;
                    v[j][i] = __ldcg(hsrc4 + (size_t)r * 128 + c * 4 + fq);
                }
            }
#pragma unroll
            for (int j = 0; j < 2; j++) {
                const int c = 2 * w + j;
#pragma unroll
                for (int i = 0; i < 2; i++) {
                    int idx = i * 32 + lane;
                    int r = idx & 15, fq = idx >> 4;
                    int kb = c * 16 + fq * 4;
                    hsh[(kb + 0) * HSH_STRIDE + (r ^ hswz(kb + 0))] = v[j][i].x;
                    hsh[(kb + 1) * HSH_STRIDE + (r ^ hswz(kb + 1))] = v[j][i].y;
                    hsh[(kb + 2) * HSH_STRIDE + (r ^ hswz(kb + 2))] = v[j][i].z;
                    hsh[(kb + 3) * HSH_STRIDE + (r ^ hswz(kb + 3))] = v[j][i].w;
                }
            }
            __syncwarp();
        }

        // ---- GEMM: 16 iterations, half-lane handles one k per iteration ----
        ull acc2[24];   // [4 rows][6 col-pairs]
#pragma unroll
        for (int i = 0; i < 24; i++) acc2[i] = 0ULL;
#pragma unroll 2
        for (int it = 0; it < 16; ++it) {
            const int k = k0 + it + half * 16;
            const float* wk = Wsh + k * WSH_STRIDE + dgi * 12;
            ull w0 = *(const ull*)(wk);
            ull w1 = *(const ull*)(wk + 2);
            ull w2 = *(const ull*)(wk + 4);
            ull w3 = *(const ull*)(wk + 6);
            ull w4 = *(const ull*)(wk + 8);
            ull w5 = *(const ull*)(wk + 10);
            const int sw = hswz(k);
            const float* hk = hsh + k * HSH_STRIDE;
            ull h0 = dup2(hk[(rb + 0) ^ sw]);
            ull h1 = dup2(hk[(rb + 1) ^ sw]);
            ull h2 = dup2(hk[(rb + 2) ^ sw]);
            ull h3 = dup2(hk[(rb + 3) ^ sw]);
            ffma2(acc2[0],  h0, w0); ffma2(acc2[1],  h0, w1); ffma2(acc2[2],  h0, w2);
            ffma2(acc2[3],  h0, w3); ffma2(acc2[4],  h0, w4); ffma2(acc2[5],  h0, w5);
            ffma2(acc2[6],  h1, w0); ffma2(acc2[7],  h1, w1); ffma2(acc2[8],  h1, w2);
            ffma2(acc2[9],  h1, w3); ffma2(acc2[10], h1, w4); ffma2(acc2[11], h1, w5);
            ffma2(acc2[12], h2, w0); ffma2(acc2[13], h2, w1); ffma2(acc2[14], h2, w2);
            ffma2(acc2[15], h2, w3); ffma2(acc2[16], h2, w4); ffma2(acc2[17], h2, w5);
            ffma2(acc2[18], h3, w0); ffma2(acc2[19], h3, w1); ffma2(acc2[20], h3, w2);
            ffma2(acc2[21], h3, w3); ffma2(acc2[22], h3, w4); ffma2(acc2[23], h3, w5);
        }

        // ---- merge halves: lane l += lane l+16 ----
#pragma unroll
        for (int i = 0; i < 24; i++) {
            ull o = __shfl_down_sync(0xffffffffu, acc2[i], 16);
            acc2[i] = add2(acc2[i], o);   // only lanes<16 hold valid sums
        }

        // ---- write partials (lanes < 16): float4 (r,z,n,0) per (row,dim) ----
        if (half == 0) {
#pragma unroll
            for (int j = 0; j < 4; j++) {
                float2 p0 = unpk2(acc2[j * 6 + 0]);   // d0r d0z
                float2 p1 = unpk2(acc2[j * 6 + 1]);   // d0n d1r
                float2 p2 = unpk2(acc2[j * 6 + 2]);   // d1z d1n
                float2 p3 = unpk2(acc2[j * 6 + 3]);   // d2r d2z
                float2 p4 = unpk2(acc2[j * 6 + 4]);   // d2n d3r
                float2 p5 = unpk2(acc2[j * 6 + 5]);   // d3z d3n
                int row = rb + j;
                float* pp = part + (((w * 16 + row) * PART_F4_RSTRIDE + dgi * 4) << 2);
                *(float4*)(pp + 0)  = make_float4(p0.x, p0.y, p1.x, 0.f);
                *(float4*)(pp + 4)  = make_float4(p1.y, p2.x, p2.y, 0.f);
                *(float4*)(pp + 8)  = make_float4(p3.x, p3.y, p4.x, 0.f);
                *(float4*)(pp + 12) = make_float4(p4.y, p5.x, p5.y, 0.f);
            }
        }
        __syncthreads();

        // ---- reduce 16 k-groups + gate, one thread per (row, dim) ----
        if (tid < 256) {
            float hr = b_r, hz = b_z, hn = b_n;
#pragma unroll
            for (int kk = 0; kk < 16; kk++) {
                float4 p = *(const float4*)(part +
                    (((kk * 16 + myrow) * PART_F4_RSTRIDE + mydl) << 2));
                hr += p.x; hz += p.y; hn += p.z;
            }
            float er = __expf(-(xr + hr));
            float rr = __fdividef(1.f, 1.f + er);
            float ez = __expf(-(xz + hz));
            float zz = __fdividef(1.f, 1.f + ez);
            float an = xn + rr * hn;
            float e2 = __expf(2.f * an);
            float nn = 1.f - __fdividef(2.f, e2 + 1.f);   // tanh(an)
            float hnew = (1.f - zz) * nn + zz * h_old;
            h_old = hnew;
            ys[((size_t)t * 64 + rowBase + myrow) * HID + mydim] = hnew;
        }

        __syncthreads();
        if (tid == 0) st_rel(&g_flags[bg][dg][0], base + (unsigned)t + 1u);
    }
}

// ---------------- final FC + sigmoid ----------------------------------------
__global__ void fc_kernel(const float* __restrict__ ys,
                          const float* __restrict__ Wfc,
                          const float* __restrict__ bfc,
                          float* __restrict__ out) {
    int b = blockIdx.x, tid = threadIdx.x;
    const float* h = ys + ((size_t)(S_LEN - 1) * 64 + b) * HID;
    float s = 0.f;
    for (int i = tid; i < HID; i += 128) s += h[i] * Wfc[i];
#pragma unroll
    for (int o = 16; o; o >>= 1) s += __shfl_down_sync(0xffffffffu, s, o);
    __shared__ float ps[4];
    if ((tid & 31) == 0) ps[tid >> 5] = s;
    __syncthreads();
    if (tid == 0) {
        float v = ps[0] + ps[1] + ps[2] + ps[3] + bfc[0];
        out[b] = 1.f / (1.f + expf(-v));
    }
}

// ---------------- launch ----------------------------------------------------
extern "C" void kernel_launch(void* const* d_in, const int* in_sizes, int n_in,
                              void* d_out, int out_size) {
    (void)in_sizes; (void)n_in; (void)out_size;
    const int*   x    = (const int*)  d_in[0];
    const float* emb  = (const float*)d_in[1];
    const float* Wih0 = (const float*)d_in[2];
    const float* Whh0 = (const float*)d_in[3];
    const float* bih0 = (const float*)d_in[4];
    const float* bhh0 = (const float*)d_in[5];
    const float* Wih1 = (const float*)d_in[6];
    const float* Whh1 = (const float*)d_in[7];
    const float* bih1 = (const float*)d_in[8];
    const float* bhh1 = (const float*)d_in[9];
    const float* Wfc  = (const float*)d_in[10];
    const float* bfc  = (const float*)d_in[11];
    float* out = (float*)d_out;

    float *xgbuf, *ysbuf;
    cudaGetSymbolAddress((void**)&xgbuf, g_xg);
    cudaGetSymbolAddress((void**)&ysbuf, g_ys);

    cudaFuncSetAttribute(gru_kernel, cudaFuncAttributeMaxDynamicSharedMemorySize,
                         GRU_SMEM_BYTES);

    // GEMM1 with fused embedding gather (A = emb_z[x])
    gemm_bias_kernel<<<dim3(G3 / 128, M_ROWS / 128), 256>>>(
        x, emb, nullptr, Wih0, bih0, xgbuf, M_ROWS, G3, EMB_D);
    gru_kernel<<<128, 512, GRU_SMEM_BYTES>>>(xgbuf, Whh0, bhh0, ysbuf);
    gemm_bias_kernel<<<dim3(G3 / 128, M_ROWS / 128), 256>>>(
        nullptr, nullptr, ysbuf, Wih1, bih1, xgbuf, M_ROWS, G3, HID);
    gru_kernel<<<128, 512, GRU_SMEM_BYTES>>>(xgbuf, Whh1, bhh1, ysbuf);
    fc_kernel<<<64, 128>>>(ysbuf, Wfc, bfc, out);
}

// round 11
// speedup vs baseline: 1.1515x; 1.1515x over previous
#include <cuda_runtime.h>
#include <math.h>

#define S_LEN 512
#define B_SZ  64
#define HID   512
#define G3    1536
#define EMB_D 256
#define M_ROWS (S_LEN * B_SZ)   // 32768

typedef unsigned long long ull;

// ---------------- packed f32x2 helpers --------------------------------------
__device__ __forceinline__ ull pk2(float lo, float hi) {
    ull r; asm("mov.b64 %0, {%1,%2};" : "=l"(r) : "f"(lo), "f"(hi)); return r;
}
__device__ __forceinline__ ull dup2(float v) { return pk2(v, v); }
__device__ __forceinline__ void ffma2(ull& d, ull a, ull b) {
    asm("fma.rn.f32x2 %0, %1, %2, %0;" : "+l"(d) : "l"(a), "l"(b));
}
__device__ __forceinline__ ull add2(ull a, ull b) {
    ull r; asm("add.rn.f32x2 %0, %1, %2;" : "=l"(r) : "l"(a), "l"(b)); return r;
}
__device__ __forceinline__ float2 unpk2(ull v) {
    float2 f; asm("mov.b64 {%0,%1}, %2;" : "=f"(f.x), "=f"(f.y) : "l"(v)); return f;
}

// ---------------- scratch (static device globals; no allocation) ------------
__device__ float g_xemb[(size_t)M_ROWS * EMB_D];   // 32 MB
__device__ float g_xg[(size_t)M_ROWS * G3];        // 192 MB
__device__ float g_ys[(size_t)M_ROWS * HID];       // 64 MB
__device__ unsigned int g_flags[4][32][32];         // one flag per 128B line

// ---------------- embedding gather ------------------------------------------
__global__ void embed_kernel(const int* __restrict__ x,
                             const float* __restrict__ emb,
                             float* __restrict__ out) {
    int w    = (blockIdx.x << 3) + (threadIdx.x >> 5);
    int lane = threadIdx.x & 31;
    int s = w >> 6, b = w & 63;
    int tok = x[b * S_LEN + s];
    float4* dst = (float4*)(out + (size_t)w * EMB_D);
    if (tok == 0) {
        float4 z = make_float4(0.f, 0.f, 0.f, 0.f);
        dst[lane] = z; dst[lane + 32] = z;
    } else {
        const float4* src = (const float4*)(emb + (size_t)tok * EMB_D);
        dst[lane] = src[lane]; dst[lane + 32] = src[lane + 32];
    }
}

// ---------------- C[M,N] = A[M,K] @ W[N,K]^T + bias[N] ----------------------
__global__ void __launch_bounds__(256, 2) gemm_bias_kernel(
    const float* __restrict__ A, const float* __restrict__ W,
    const float* __restrict__ bias, float* __restrict__ C,
    int M, int N, int K) {
    __shared__ float As[2][16][128];
    __shared__ float Bs[2][16][128];

    const int tid = threadIdx.x;
    const int n0 = blockIdx.x * 128;
    const int m0 = blockIdx.y * 128;
    const int tx = tid & 15, ty = tid >> 4;

    ull acc2[4][8];
#pragma unroll
    for (int p = 0; p < 4; p++)
#pragma unroll
        for (int j = 0; j < 8; j++) acc2[p][j] = 0ULL;

    const int KT = K >> 4;

#pragma unroll
    for (int i = 0; i < 2; i++) {
        int id = tid * 2 + i, row = id >> 2, kq = id & 3;
        float4 va = *(const float4*)(A + (size_t)(m0 + row) * K + kq * 4);
        float4 vb = *(const float4*)(W + (size_t)(n0 + row) * K + kq * 4);
        As[0][kq * 4 + 0][row] = va.x; As[0][kq * 4 + 1][row] = va.y;
        As[0][kq * 4 + 2][row] = va.z; As[0][kq * 4 + 3][row] = va.w;
        Bs[0][kq * 4 + 0][row] = vb.x; Bs[0][kq * 4 + 1][row] = vb.y;
        Bs[0][kq * 4 + 2][row] = vb.z; Bs[0][kq * 4 + 3][row] = vb.w;
    }
    __syncthreads();

    for (int kt = 0; kt < KT; ++kt) {
        const int cur = kt & 1;
        float4 pa[2], pb[2];
        const bool pf = (kt + 1) < KT;
        if (pf) {
#pragma unroll
            for (int i = 0; i < 2; i++) {
                int id = tid * 2 + i, row = id >> 2, kq = id & 3;
                pa[i] = *(const float4*)(A + (size_t)(m0 + row) * K + (kt + 1) * 16 + kq * 4);
                pb[i] = *(const float4*)(W + (size_t)(n0 + row) * K + (kt + 1) * 16 + kq * 4);
            }
        }
#pragma unroll
        for (int kk = 0; kk < 16; kk++) {
            ulonglong2 a01 = *(const ulonglong2*)&As[cur][kk][ty * 4];
            ulonglong2 a23 = *(const ulonglong2*)&As[cur][kk][64 + ty * 4];
            ull ap[4] = { a01.x, a01.y, a23.x, a23.y };
            float b[8];
            *(float4*)(b)     = *(const float4*)&Bs[cur][kk][tx * 4];
            *(float4*)(b + 4) = *(const float4*)&Bs[cur][kk][64 + tx * 4];
#pragma unroll
            for (int j = 0; j < 8; j++) {
                ull bd = dup2(b[j]);
#pragma unroll
                for (int p = 0; p < 4; p++) ffma2(acc2[p][j], ap[p], bd);
            }
        }
        if (pf) {
            const int nxt = cur ^ 1;
#pragma unroll
            for (int i = 0; i < 2; i++) {
                int id = tid * 2 + i, row = id >> 2, kq = id & 3;
                As[nxt][kq * 4 + 0][row] = pa[i].x; As[nxt][kq * 4 + 1][row] = pa[i].y;
                As[nxt][kq * 4 + 2][row] = pa[i].z; As[nxt][kq * 4 + 3][row] = pa[i].w;
                Bs[nxt][kq * 4 + 0][row] = pb[i].x; Bs[nxt][kq * 4 + 1][row] = pb[i].y;
                Bs[nxt][kq * 4 + 2][row] = pb[i].z; Bs[nxt][kq * 4 + 3][row] = pb[i].w;
            }
        }
        __syncthreads();
    }

    float4 bb0 = *(const float4*)&bias[n0 + tx * 4];
    float4 bb1 = *(const float4*)&bias[n0 + 64 + tx * 4];
#pragma unroll
    for (int p = 0; p < 4; p++) {
        float2 c[8];
#pragma unroll
        for (int j = 0; j < 8; j++) c[j] = unpk2(acc2[p][j]);
#pragma unroll
        for (int half = 0; half < 2; half++) {
            int i = 2 * p + half;
            int m = m0 + ((i < 4) ? (ty * 4 + i) : (64 + ty * 4 + i - 4));
            float e[8];
#pragma unroll
            for (int j = 0; j < 8; j++) e[j] = half ? c[j].y : c[j].x;
            float4 v0 = make_float4(e[0] + bb0.x, e[1] + bb0.y,
                                    e[2] + bb0.z, e[3] + bb0.w);
            float4 v1 = make_float4(e[4] + bb1.x, e[5] + bb1.y,
                                    e[6] + bb1.z, e[7] + bb1.w);
            *(float4*)(C + (size_t)m * N + n0 + tx * 4)      = v0;
            *(float4*)(C + (size_t)m * N + n0 + 64 + tx * 4) = v1;
        }
    }
}

// ---------------- GRU recurrence ---------------------------------------------
// 128 blocks = 4 batch groups (16 rows) x 32 dim groups (16 dims), 512 threads.
// Warp w owns k in [32w, 32w+32); lanes 0-15 take even k, lanes 16-31 odd k.
// Lane (l = lane&15) owns dim l: ALL 16 rows x 3 gates. W reads have ZERO
// lane redundancy (16 lanes = 48 gate-cols); gate-major W layout (col=g*16+l,
// stride 48 == 16 mod 32) puts even/odd halves on disjoint bank halves ->
// 1 wavefront per W LDS.32. h read as 8 broadcast LDS.64 per k.
#define WSH_STRIDE 48
#define HS 16
#define P4STRIDE 17
#define GRU_SMEM_FLOATS (512 * WSH_STRIDE + 512 * HS + 16 * 16 * P4STRIDE * 4)
#define GRU_SMEM_BYTES  (GRU_SMEM_FLOATS * 4)

__device__ __forceinline__ unsigned ld_acq(const unsigned* p) {
    unsigned v;
    asm volatile("ld.global.acquire.gpu.u32 %0, [%1];" : "=r"(v) : "l"(p) : "memory");
    return v;
}
__device__ __forceinline__ void st_rel(unsigned* p, unsigned v) {
    asm volatile("st.global.release.gpu.u32 [%0], %1;" :: "l"(p), "r"(v) : "memory");
}

__global__ void __launch_bounds__(512, 1) gru_kernel(
    const float* __restrict__ xg,    // [S][64][1536]
    const float* __restrict__ Whh,   // [1536][512]
    const float* __restrict__ bhh,   // [1536]
    float* __restrict__ ys)          // [S][64][512]
{
    extern __shared__ float sm[];
    float* Wsh  = sm;                          // 512*48
    float* hsh  = Wsh + 512 * WSH_STRIDE;      // 512*16
    float* part = hsh + 512 * HS;              // 16*16*17*4
    __shared__ unsigned sh_base;

    const int tid = threadIdx.x;
    const int bg  = blockIdx.x & 3;
    const int dg  = blockIdx.x >> 2;
    const int rowBase = bg * 16;
    const int dimBase = dg * 16;

    if (tid == 0) sh_base = *(volatile unsigned*)&g_flags[bg][dg][0];

    // load W_hh slice into smem, k-major, GATE-MAJOR cols (col = g*16 + dl)
    for (int idx = tid; idx < 48 * 512; idx += 512) {
        int col = idx >> 9;       // 0..47
        int k   = idx & 511;
        int g = col >> 4, dl = col & 15;
        int grow = g * 512 + dimBase + dl;
        Wsh[k * WSH_STRIDE + col] = Whh[(size_t)grow * 512 + k];
    }

    // gating role (tid < 256): one thread per (row, dim); h_old in a register
    const int myrow = (tid >> 4) & 15;
    const int mydl  = tid & 15;
    const int mydim = dimBase + mydl;
    float b_r = 0.f, b_z = 0.f, b_n = 0.f;
    float h_old = 0.f;
    if (tid < 256) {
        b_r = bhh[mydim]; b_z = bhh[512 + mydim]; b_n = bhh[1024 + mydim];
    }

    // compute role
    const int w    = tid >> 5;            // warp 0..15, k chunk [32w, 32w+32)
    const int lane = tid & 31;
    const int half = lane >> 4;           // 0: even k, 1: odd k
    const int l    = lane & 15;           // owned dim (local)
    const int k0   = w * 32;

    __syncthreads();
    const unsigned base = sh_base;

    for (int t = 0; t < S_LEN; ++t) {
        // xg prefetch for gating
        float xr = 0.f, xz = 0.f, xn = 0.f;
        if (tid < 256) {
            size_t xbase = ((size_t)t * 64 + rowBase + myrow) * G3 + mydim;
            xr = xg[xbase]; xz = xg[xbase + 512]; xn = xg[xbase + 1024];
        }

        // ---- warp-private h staging (h stored [k][row], stride 16) ----
        if (t == 0) {
            for (int idx = lane; idx < 32 * HS; idx += 32)
                hsh[k0 * HS + idx] = 0.f;
            __syncwarp();
        } else {
            const unsigned target = base + (unsigned)t;
            const float4* hsrc4 = (const float4*)(ys + ((size_t)(t - 1) * 64 + rowBase) * HID);
            float4 v[2][2];
#pragma unroll
            for (int j = 0; j < 2; j++) {
                const int c = 2 * w + j;   // producer chunk (16 dims = 16 k)
                const unsigned* fp = &g_flags[bg][c][0];
                while ((int)(ld_acq(fp) - target) < 0) { }
#pragma unroll
                for (int i = 0; i < 2; i++) {
                    int idx = i * 32 + lane;
                    int r = idx & 15, fq = idx >> 4;
                    v[j][i] = __ldcg(hsrc4 + (size_t)r * 128 + c * 4 + fq);
                }
            }
#pragma unroll
            for (int j = 0; j < 2; j++) {
                const int c = 2 * w + j;
#pragma unroll
                for (int i = 0; i < 2; i++) {
                    int idx = i * 32 + lane;
                    int r = idx & 15, fq = idx >> 4;
                    int kb = c * 16 + fq * 4;
                    hsh[(kb + 0) * HS + r] = v[j][i].x;
                    hsh[(kb + 1) * HS + r] = v[j][i].y;
                    hsh[(kb + 2) * HS + r] = v[j][i].z;
                    hsh[(kb + 3) * HS + r] = v[j][i].w;
                }
            }
            __syncwarp();
        }

        // ---- GEMM: lane owns dim l, 16 rows (8 row-pairs), 3 gates ----
        ull acc[24];   // [rowpair j][gate g] = acc[j*3+g]
#pragma unroll
        for (int i = 0; i < 24; i++) acc[i] = 0ULL;
#pragma unroll 4
        for (int it = 0; it < 16; ++it) {
            const int k = k0 + 2 * it + half;
            const float* wk = Wsh + k * WSH_STRIDE + l;
            ull wr2 = dup2(wk[0]);
            ull wz2 = dup2(wk[16]);
            ull wn2 = dup2(wk[32]);
            const float* hk = hsh + k * HS;
            ull hp[8];
#pragma unroll
            for (int j = 0; j < 8; j++) hp[j] = *(const ull*)(hk + 2 * j);
#pragma unroll
            for (int j = 0; j < 8; j++) {
                ffma2(acc[j * 3 + 0], hp[j], wr2);
                ffma2(acc[j * 3 + 1], hp[j], wz2);
                ffma2(acc[j * 3 + 2], hp[j], wn2);
            }
        }

        // ---- merge halves (even k + odd k) ----
#pragma unroll
        for (int i = 0; i < 24; i++) {
            ull o = __shfl_down_sync(0xffffffffu, acc[i], 16);
            acc[i] = add2(acc[i], o);   // lanes<16 hold full 32-k sums
        }

        // ---- write partials (lanes < 16): float4 (r,z,n,0) per row ----
        if (half == 0) {
#pragma unroll
            for (int j = 0; j < 8; j++) {
                float2 r2 = unpk2(acc[j * 3 + 0]);
                float2 z2 = unpk2(acc[j * 3 + 1]);
                float2 n2 = unpk2(acc[j * 3 + 2]);
                float* pp0 = part + (((w * 16 + 2 * j) * P4STRIDE + l) << 2);
                float* pp1 = part + (((w * 16 + 2 * j + 1) * P4STRIDE + l) << 2);
                *(float4*)pp0 = make_float4(r2.x, z2.x, n2.x, 0.f);
                *(float4*)pp1 = make_float4(r2.y, z2.y, n2.y, 0.f);
            }
        }
        __syncthreads();

        // ---- reduce 16 k-groups + gate, one thread per (row, dim) ----
        if (tid < 256) {
            float hr = b_r, hz = b_z, hn = b_n;
#pragma unroll
            for (int kk = 0; kk < 16; kk++) {
                float4 p = *(const float4*)(part +
                    (((kk * 16 + myrow) * P4STRIDE + mydl) << 2));
                hr += p.x; hz += p.y; hn += p.z;
            }
            float er = __expf(-(xr + hr));
            float rr = __fdividef(1.f, 1.f + er);
            float ez = __expf(-(xz + hz));
            float zz = __fdividef(1.f, 1.f + ez);
            float an = xn + rr * hn;
            float e2 = __expf(2.f * an);
            float nn = 1.f - __fdividef(2.f, e2 + 1.f);   // tanh(an)
            float hnew = (1.f - zz) * nn + zz * h_old;
            h_old = hnew;
            ys[((size_t)t * 64 + rowBase + myrow) * HID + mydim] = hnew;
        }

        __syncthreads();
        if (tid == 0) st_rel(&g_flags[bg][dg][0], base + (unsigned)t + 1u);
    }
}

// ---------------- final FC + sigmoid ----------------------------------------
__global__ void fc_kernel(const float* __restrict__ ys,
                          const float* __restrict__ Wfc,
                          const float* __restrict__ bfc,
                          float* __restrict__ out) {
    int b = blockIdx.x, tid = threadIdx.x;
    const float* h = ys + ((size_t)(S_LEN - 1) * 64 + b) * HID;
    float s = 0.f;
    for (int i = tid; i < HID; i += 128) s += h[i] * Wfc[i];
#pragma unroll
    for (int o = 16; o; o >>= 1) s += __shfl_down_sync(0xffffffffu, s, o);
    __shared__ float ps[4];
    if ((tid & 31) == 0) ps[tid >> 5] = s;
    __syncthreads();
    if (tid == 0) {
        float v = ps[0] + ps[1] + ps[2] + ps[3] + bfc[0];
        out[b] = 1.f / (1.f + expf(-v));
    }
}

// ---------------- launch ----------------------------------------------------
extern "C" void kernel_launch(void* const* d_in, const int* in_sizes, int n_in,
                              void* d_out, int out_size) {
    (void)in_sizes; (void)n_in; (void)out_size;
    const int*   x    = (const int*)  d_in[0];
    const float* emb  = (const float*)d_in[1];
    const float* Wih0 = (const float*)d_in[2];
    const float* Whh0 = (const float*)d_in[3];
    const float* bih0 = (const float*)d_in[4];
    const float* bhh0 = (const float*)d_in[5];
    const float* Wih1 = (const float*)d_in[6];
    const float* Whh1 = (const float*)d_in[7];
    const float* bih1 = (const float*)d_in[8];
    const float* bhh1 = (const float*)d_in[9];
    const float* Wfc  = (const float*)d_in[10];
    const float* bfc  = (const float*)d_in[11];
    float* out = (float*)d_out;

    float *xemb, *xgbuf, *ysbuf;
    cudaGetSymbolAddress((void**)&xemb,  g_xemb);
    cudaGetSymbolAddress((void**)&xgbuf, g_xg);
    cudaGetSymbolAddress((void**)&ysbuf, g_ys);

    cudaFuncSetAttribute(gru_kernel, cudaFuncAttributeMaxDynamicSharedMemorySize,
                         GRU_SMEM_BYTES);

    embed_kernel<<<4096, 256>>>(x, emb, xemb);
    gemm_bias_kernel<<<dim3(G3 / 128, M_ROWS / 128), 256>>>(
        xemb, Wih0, bih0, xgbuf, M_ROWS, G3, EMB_D);
    gru_kernel<<<128, 512, GRU_SMEM_BYTES>>>(xgbuf, Whh0, bhh0, ysbuf);
    gemm_bias_kernel<<<dim3(G3 / 128, M_ROWS / 128), 256>>>(
        ysbuf, Wih1, bih1, xgbuf, M_ROWS, G3, HID);
    gru_kernel<<<128, 512, GRU_SMEM_BYTES>>>(xgbuf, Whh1, bhh1, ysbuf);
    fc_kernel<<<64, 128>>>(ysbuf, Wfc, bfc, out);
}

// round 12
// speedup vs baseline: 1.1955x; 1.0382x over previous
#include <cuda_runtime.h>
#include <math.h>

#define S_LEN 512
#define B_SZ  64
#define HID   512
#define G3    1536
#define EMB_D 256
#define M_ROWS (S_LEN * B_SZ)   // 32768

typedef unsigned long long ull;

// ---------------- packed f32x2 helpers --------------------------------------
__device__ __forceinline__ ull pk2(float lo, float hi) {
    ull r; asm("mov.b64 %0, {%1,%2};" : "=l"(r) : "f"(lo), "f"(hi)); return r;
}
__device__ __forceinline__ ull dup2(float v) { return pk2(v, v); }
__device__ __forceinline__ void ffma2(ull& d, ull a, ull b) {
    asm("fma.rn.f32x2 %0, %1, %2, %0;" : "+l"(d) : "l"(a), "l"(b));
}
__device__ __forceinline__ ull add2(ull a, ull b) {
    ull r; asm("add.rn.f32x2 %0, %1, %2;" : "=l"(r) : "l"(a), "l"(b)); return r;
}
__device__ __forceinline__ float2 unpk2(ull v) {
    float2 f; asm("mov.b64 {%0,%1}, %2;" : "=f"(f.x), "=f"(f.y) : "l"(v)); return f;
}

// ---------------- scratch (static device globals; no allocation) ------------
__device__ float g_xemb[(size_t)M_ROWS * EMB_D];   // 32 MB
__device__ float g_xg[(size_t)M_ROWS * G3];        // 192 MB
__device__ float g_ys[(size_t)M_ROWS * HID];       // 64 MB
__device__ unsigned int g_flags[4][32][32];         // one flag per 128B line

// ---------------- embedding gather ------------------------------------------
__global__ void embed_kernel(const int* __restrict__ x,
                             const float* __restrict__ emb,
                             float* __restrict__ out) {
    int w    = (blockIdx.x << 3) + (threadIdx.x >> 5);
    int lane = threadIdx.x & 31;
    int s = w >> 6, b = w & 63;
    int tok = x[b * S_LEN + s];
    float4* dst = (float4*)(out + (size_t)w * EMB_D);
    if (tok == 0) {
        float4 z = make_float4(0.f, 0.f, 0.f, 0.f);
        dst[lane] = z; dst[lane + 32] = z;
    } else {
        const float4* src = (const float4*)(emb + (size_t)tok * EMB_D);
        dst[lane] = src[lane]; dst[lane + 32] = src[lane + 32];
    }
}

// ---------------- C[M,N] = A[M,K] @ W[N,K]^T + bias[N] ----------------------
__global__ void __launch_bounds__(256, 2) gemm_bias_kernel(
    const float* __restrict__ A, const float* __restrict__ W,
    const float* __restrict__ bias, float* __restrict__ C,
    int M, int N, int K) {
    __shared__ float As[2][16][128];
    __shared__ float Bs[2][16][128];

    const int tid = threadIdx.x;
    const int n0 = blockIdx.x * 128;
    const int m0 = blockIdx.y * 128;
    const int tx = tid & 15, ty = tid >> 4;

    ull acc2[4][8];
#pragma unroll
    for (int p = 0; p < 4; p++)
#pragma unroll
        for (int j = 0; j < 8; j++) acc2[p][j] = 0ULL;

    const int KT = K >> 4;

#pragma unroll
    for (int i = 0; i < 2; i++) {
        int id = tid * 2 + i, row = id >> 2, kq = id & 3;
        float4 va = *(const float4*)(A + (size_t)(m0 + row) * K + kq * 4);
        float4 vb = *(const float4*)(W + (size_t)(n0 + row) * K + kq * 4);
        As[0][kq * 4 + 0][row] = va.x; As[0][kq * 4 + 1][row] = va.y;
        As[0][kq * 4 + 2][row] = va.z; As[0][kq * 4 + 3][row] = va.w;
        Bs[0][kq * 4 + 0][row] = vb.x; Bs[0][kq * 4 + 1][row] = vb.y;
        Bs[0][kq * 4 + 2][row] = vb.z; Bs[0][kq * 4 + 3][row] = vb.w;
    }
    __syncthreads();

    for (int kt = 0; kt < KT; ++kt) {
        const int cur = kt & 1;
        float4 pa[2], pb[2];
        const bool pf = (kt + 1) < KT;
        if (pf) {
#pragma unroll
            for (int i = 0; i < 2; i++) {
                int id = tid * 2 + i, row = id >> 2, kq = id & 3;
                pa[i] = *(const float4*)(A + (size_t)(m0 + row) * K + (kt + 1) * 16 + kq * 4);
                pb[i] = *(const float4*)(W + (size_t)(n0 + row) * K + (kt + 1) * 16 + kq * 4);
            }
        }
#pragma unroll
        for (int kk = 0; kk < 16; kk++) {
            ulonglong2 a01 = *(const ulonglong2*)&As[cur][kk][ty * 4];
            ulonglong2 a23 = *(const ulonglong2*)&As[cur][kk][64 + ty * 4];
            ull ap[4] = { a01.x, a01.y, a23.x, a23.y };
            float b[8];
            *(float4*)(b)     = *(const float4*)&Bs[cur][kk][tx * 4];
            *(float4*)(b + 4) = *(const float4*)&Bs[cur][kk][64 + tx * 4];
#pragma unroll
            for (int j = 0; j < 8; j++) {
                ull bd = dup2(b[j]);
#pragma unroll
                for (int p = 0; p < 4; p++) ffma2(acc2[p][j], ap[p], bd);
            }
        }
        if (pf) {
            const int nxt = cur ^ 1;
#pragma unroll
            for (int i = 0; i < 2; i++) {
                int id = tid * 2 + i, row = id >> 2, kq = id & 3;
                As[nxt][kq * 4 + 0][row] = pa[i].x; As[nxt][kq * 4 + 1][row] = pa[i].y;
                As[nxt][kq * 4 + 2][row] = pa[i].z; As[nxt][kq * 4 + 3][row] = pa[i].w;
                Bs[nxt][kq * 4 + 0][row] = pb[i].x; Bs[nxt][kq * 4 + 1][row] = pb[i].y;
                Bs[nxt][kq * 4 + 2][row] = pb[i].z; Bs[nxt][kq * 4 + 3][row] = pb[i].w;
            }
        }
        __syncthreads();
    }

    float4 bb0 = *(const float4*)&bias[n0 + tx * 4];
    float4 bb1 = *(const float4*)&bias[n0 + 64 + tx * 4];
#pragma unroll
    for (int p = 0; p < 4; p++) {
        float2 c[8];
#pragma unroll
        for (int j = 0; j < 8; j++) c[j] = unpk2(acc2[p][j]);
#pragma unroll
        for (int half = 0; half < 2; half++) {
            int i = 2 * p + half;
            int m = m0 + ((i < 4) ? (ty * 4 + i) : (64 + ty * 4 + i - 4));
            float e[8];
#pragma unroll
            for (int j = 0; j < 8; j++) e[j] = half ? c[j].y : c[j].x;
            float4 v0 = make_float4(e[0] + bb0.x, e[1] + bb0.y,
                                    e[2] + bb0.z, e[3] + bb0.w);
            float4 v1 = make_float4(e[4] + bb1.x, e[5] + bb1.y,
                                    e[6] + bb1.z, e[7] + bb1.w);
            *(float4*)(C + (size_t)m * N + n0 + tx * 4)      = v0;
            *(float4*)(C + (size_t)m * N + n0 + 64 + tx * 4) = v1;
        }
    }
}

// ---------------- GRU recurrence ---------------------------------------------
// 128 blocks = 4 batch groups (16 rows) x 32 dim groups (16 dims), 512 threads.
// Warp w owns k in [32w, 32w+32); lanes 0-15 take even k, lanes 16-31 odd k.
// Lane (l = lane&15) owns dim l: all 16 rows x 3 gates.
// hsh stride 20 floats: rows 16B-aligned; even/odd-k rows land on disjoint
// bank ranges -> broadcast LDS.128 h loads and conflict-free staging STS.
#define WSH_STRIDE 48
#define HS 20
#define P4STRIDE 17
#define GRU_SMEM_FLOATS (512 * WSH_STRIDE + 512 * HS + 16 * 16 * P4STRIDE * 4)
#define GRU_SMEM_BYTES  (GRU_SMEM_FLOATS * 4)

__device__ __forceinline__ unsigned ld_acq(const unsigned* p) {
    unsigned v;
    asm volatile("ld.global.acquire.gpu.u32 %0, [%1];" : "=r"(v) : "l"(p) : "memory");
    return v;
}
__device__ __forceinline__ void st_rel(unsigned* p, unsigned v) {
    asm volatile("st.global.release.gpu.u32 [%0], %1;" :: "l"(p), "r"(v) : "memory");
}

__global__ void __launch_bounds__(512, 1) gru_kernel(
    const float* __restrict__ xg,    // [S][64][1536]
    const float* __restrict__ Whh,   // [1536][512]
    const float* __restrict__ bhh,   // [1536]
    float* __restrict__ ys)          // [S][64][512]
{
    extern __shared__ float sm[];
    float* Wsh  = sm;                          // 512*48
    float* hsh  = Wsh + 512 * WSH_STRIDE;      // 512*20
    float* part = hsh + 512 * HS;              // 16*16*17*4
    __shared__ unsigned sh_base;

    const int tid = threadIdx.x;
    const int bg  = blockIdx.x & 3;
    const int dg  = blockIdx.x >> 2;
    const int rowBase = bg * 16;
    const int dimBase = dg * 16;

    if (tid == 0) sh_base = *(volatile unsigned*)&g_flags[bg][dg][0];

    // load W_hh slice into smem, k-major, GATE-MAJOR cols (col = g*16 + dl)
    for (int idx = tid; idx < 48 * 512; idx += 512) {
        int col = idx >> 9;       // 0..47
        int k   = idx & 511;
        int g = col >> 4, dl = col & 15;
        int grow = g * 512 + dimBase + dl;
        Wsh[k * WSH_STRIDE + col] = Whh[(size_t)grow * 512 + k];
    }

    // gating role (tid < 256): one thread per (row, dim); h_old in a register
    const int myrow = (tid >> 4) & 15;
    const int mydl  = tid & 15;
    const int mydim = dimBase + mydl;
    float b_r = 0.f, b_z = 0.f, b_n = 0.f;
    float h_old = 0.f;
    if (tid < 256) {
        b_r = bhh[mydim]; b_z = bhh[512 + mydim]; b_n = bhh[1024 + mydim];
    }

    // compute role
    const int w    = tid >> 5;            // warp 0..15, k chunk [32w, 32w+32)
    const int lane = tid & 31;
    const int half = lane >> 4;           // 0: even k, 1: odd k
    const int l    = lane & 15;           // owned dim (local)
    const int k0   = w * 32;

    __syncthreads();
    const unsigned base = sh_base;

    for (int t = 0; t < S_LEN; ++t) {
        // xg prefetch for gating
        float xr = 0.f, xz = 0.f, xn = 0.f;
        if (tid < 256) {
            size_t xbase = ((size_t)t * 64 + rowBase + myrow) * G3 + mydim;
            xr = xg[xbase]; xz = xg[xbase + 512]; xn = xg[xbase + 1024];
        }

        // ---- warp-private h staging (h stored [k][row], stride 20) ----
        if (t == 0) {
            for (int idx = lane; idx < 32 * HS; idx += 32)
                hsh[k0 * HS + idx] = 0.f;
            __syncwarp();
        } else {
            const unsigned target = base + (unsigned)t;
            const float4* hsrc4 = (const float4*)(ys + ((size_t)(t - 1) * 64 + rowBase) * HID);
            float4 v[2][2];
#pragma unroll
            for (int j = 0; j < 2; j++) {
                const int c = 2 * w + j;   // producer chunk (16 dims = 16 k)
                const unsigned* fp = &g_flags[bg][c][0];
                while ((int)(ld_acq(fp) - target) < 0) { }
#pragma unroll
                for (int i = 0; i < 2; i++) {
                    int idx = i * 32 + lane;
                    int r = idx & 15, fq = idx >> 4;
                    v[j][i] = __ldcg(hsrc4 + (size_t)r * 128 + c * 4 + fq);
                }
            }
#pragma unroll
            for (int j = 0; j < 2; j++) {
                const int c = 2 * w + j;
#pragma unroll
                for (int i = 0; i < 2; i++) {
                    int idx = i * 32 + lane;
                    int r = idx & 15, fq = idx >> 4;
                    int kb = c * 16 + fq * 4;
                    hsh[(kb + 0) * HS + r] = v[j][i].x;
                    hsh[(kb + 1) * HS + r] = v[j][i].y;
                    hsh[(kb + 2) * HS + r] = v[j][i].z;
                    hsh[(kb + 3) * HS + r] = v[j][i].w;
                }
            }
            __syncwarp();
        }

        // ---- GEMM: lane owns dim l, 16 rows (8 row-pairs), 3 gates ----
        ull acc[24];   // [rowpair j][gate g] = acc[j*3+g]
#pragma unroll
        for (int i = 0; i < 24; i++) acc[i] = 0ULL;
#pragma unroll 4
        for (int it = 0; it < 16; ++it) {
            const int k = k0 + 2 * it + half;
            const float* wk = Wsh + k * WSH_STRIDE + l;
            ull wr2 = dup2(wk[0]);
            ull wz2 = dup2(wk[16]);
            ull wn2 = dup2(wk[32]);
            const float* hk = hsh + k * HS;
            ulonglong2 hq[4];
#pragma unroll
            for (int q = 0; q < 4; q++) hq[q] = *(const ulonglong2*)(hk + 4 * q);
            ull hp[8] = { hq[0].x, hq[0].y, hq[1].x, hq[1].y,
                          hq[2].x, hq[2].y, hq[3].x, hq[3].y };
#pragma unroll
            for (int j = 0; j < 8; j++) {
                ffma2(acc[j * 3 + 0], hp[j], wr2);
                ffma2(acc[j * 3 + 1], hp[j], wz2);
                ffma2(acc[j * 3 + 2], hp[j], wn2);
            }
        }

        // ---- merge halves (even k + odd k) ----
#pragma unroll
        for (int i = 0; i < 24; i++) {
            ull o = __shfl_down_sync(0xffffffffu, acc[i], 16);
            acc[i] = add2(acc[i], o);   // lanes<16 hold full 32-k sums
        }

        // ---- write partials (lanes < 16): float4 (r,z,n,0) per row ----
        if (half == 0) {
#pragma unroll
            for (int j = 0; j < 8; j++) {
                float2 r2 = unpk2(acc[j * 3 + 0]);
                float2 z2 = unpk2(acc[j * 3 + 1]);
                float2 n2 = unpk2(acc[j * 3 + 2]);
                float* pp0 = part + (((w * 16 + 2 * j) * P4STRIDE + l) << 2);
                float* pp1 = part + (((w * 16 + 2 * j + 1) * P4STRIDE + l) << 2);
                *(float4*)pp0 = make_float4(r2.x, z2.x, n2.x, 0.f);
                *(float4*)pp1 = make_float4(r2.y, z2.y, n2.y, 0.f);
            }
        }
        __syncthreads();

        // ---- reduce 16 k-groups + gate, one thread per (row, dim) ----
        if (tid < 256) {
            float hr = b_r, hz = b_z, hn = b_n;
#pragma unroll
            for (int kk = 0; kk < 16; kk++) {
                float4 p = *(const float4*)(part +
                    (((kk * 16 + myrow) * P4STRIDE + mydl) << 2));
                hr += p.x; hz += p.y; hn += p.z;
            }
            float er = __expf(-(xr + hr));
            float rr = __fdividef(1.f, 1.f + er);
            float ez = __expf(-(xz + hz));
            float zz = __fdividef(1.f, 1.f + ez);
            float an = xn + rr * hn;
            float e2 = __expf(2.f * an);
            float nn = 1.f - __fdividef(2.f, e2 + 1.f);   // tanh(an)
            float hnew = (1.f - zz) * nn + zz * h_old;
            h_old = hnew;
            ys[((size_t)t * 64 + rowBase + myrow) * HID + mydim] = hnew;
        }

        __syncthreads();
        if (tid == 0) st_rel(&g_flags[bg][dg][0], base + (unsigned)t + 1u);
    }
}

// ---------------- final FC + sigmoid ----------------------------------------
__global__ void fc_kernel(const float* __restrict__ ys,
                          const float* __restrict__ Wfc,
                          const float* __restrict__ bfc,
                          float* __restrict__ out) {
    int b = blockIdx.x, tid = threadIdx.x;
    const float* h = ys + ((size_t)(S_LEN - 1) * 64 + b) * HID;
    float s = 0.f;
    for (int i = tid; i < HID; i += 128) s += h[i] * Wfc[i];
#pragma unroll
    for (int o = 16; o; o >>= 1) s += __shfl_down_sync(0xffffffffu, s, o);
    __shared__ float ps[4];
    if ((tid & 31) == 0) ps[tid >> 5] = s;
    __syncthreads();
    if (tid == 0) {
        float v = ps[0] + ps[1] + ps[2] + ps[3] + bfc[0];
        out[b] = 1.f / (1.f + expf(-v));
    }
}

// ---------------- launch ----------------------------------------------------
extern "C" void kernel_launch(void* const* d_in, const int* in_sizes, int n_in,
                              void* d_out, int out_size) {
    (void)in_sizes; (void)n_in; (void)out_size;
    const int*   x    = (const int*)  d_in[0];
    const float* emb  = (const float*)d_in[1];
    const float* Wih0 = (const float*)d_in[2];
    const float* Whh0 = (const float*)d_in[3];
    const float* bih0 = (const float*)d_in[4];
    const float* bhh0 = (const float*)d_in[5];
    const float* Wih1 = (const float*)d_in[6];
    const float* Whh1 = (const float*)d_in[7];
    const float* bih1 = (const float*)d_in[8];
    const float* bhh1 = (const float*)d_in[9];
    const float* Wfc  = (const float*)d_in[10];
    const float* bfc  = (const float*)d_in[11];
    float* out = (float*)d_out;

    float *xemb, *xgbuf, *ysbuf;
    cudaGetSymbolAddress((void**)&xemb,  g_xemb);
    cudaGetSymbolAddress((void**)&xgbuf, g_xg);
    cudaGetSymbolAddress((void**)&ysbuf, g_ys);

    cudaFuncSetAttribute(gru_kernel, cudaFuncAttributeMaxDynamicSharedMemorySize,
                         GRU_SMEM_BYTES);

    embed_kernel<<<4096, 256>>>(x, emb, xemb);
    gemm_bias_kernel<<<dim3(G3 / 128, M_ROWS / 128), 256>>>(
        xemb, Wih0, bih0, xgbuf, M_ROWS, G3, EMB_D);
    gru_kernel<<<128, 512, GRU_SMEM_BYTES>>>(xgbuf, Whh0, bhh0, ysbuf);
    gemm_bias_kernel<<<dim3(G3 / 128, M_ROWS / 128), 256>>>(
        ysbuf, Wih1, bih1, xgbuf, M_ROWS, G3, HID);
    gru_kernel<<<128, 512, GRU_SMEM_BYTES>>>(xgbuf, Whh1, bhh1, ysbuf);
    fc_kernel<<<64, 128>>>(ysbuf, Wfc, bfc, out);
}

// round 13
// speedup vs baseline: 1.2025x; 1.0059x over previous
#include <cuda_runtime.h>
#include <math.h>

#define S_LEN 512
#define B_SZ  64
#define HID   512
#define G3    1536
#define EMB_D 256
#define M_ROWS (S_LEN * B_SZ)   // 32768

typedef unsigned long long ull;

// ---------------- packed f32x2 helpers --------------------------------------
__device__ __forceinline__ ull pk2(float lo, float hi) {
    ull r; asm("mov.b64 %0, {%1,%2};" : "=l"(r) : "f"(lo), "f"(hi)); return r;
}
__device__ __forceinline__ ull dup2(float v) { return pk2(v, v); }
__device__ __forceinline__ void ffma2(ull& d, ull a, ull b) {
    asm("fma.rn.f32x2 %0, %1, %2, %0;" : "+l"(d) : "l"(a), "l"(b));
}
__device__ __forceinline__ ull add2(ull a, ull b) {
    ull r; asm("add.rn.f32x2 %0, %1, %2;" : "=l"(r) : "l"(a), "l"(b)); return r;
}
__device__ __forceinline__ float2 unpk2(ull v) {
    float2 f; asm("mov.b64 {%0,%1}, %2;" : "=f"(f.x), "=f"(f.y) : "l"(v)); return f;
}

// ---------------- scratch (static device globals; no allocation) ------------
__device__ float g_xemb[(size_t)M_ROWS * EMB_D];   // 32 MB
__device__ float g_xg[(size_t)M_ROWS * G3];        // 192 MB
__device__ float g_ys[(size_t)M_ROWS * HID];       // 64 MB
__device__ unsigned int g_flags[4][32][32];         // one flag per 128B line

// ---------------- embedding gather ------------------------------------------
__global__ void embed_kernel(const int* __restrict__ x,
                             const float* __restrict__ emb,
                             float* __restrict__ out) {
    int w    = (blockIdx.x << 3) + (threadIdx.x >> 5);
    int lane = threadIdx.x & 31;
    int s = w >> 6, b = w & 63;
    int tok = x[b * S_LEN + s];
    float4* dst = (float4*)(out + (size_t)w * EMB_D);
    if (tok == 0) {
        float4 z = make_float4(0.f, 0.f, 0.f, 0.f);
        dst[lane] = z; dst[lane + 32] = z;
    } else {
        const float4* src = (const float4*)(emb + (size_t)tok * EMB_D);
        dst[lane] = src[lane]; dst[lane + 32] = src[lane + 32];
    }
}

// ---------------- C[M,N] = A[M,K] @ W[N,K]^T + bias[N] ----------------------
__global__ void __launch_bounds__(256, 2) gemm_bias_kernel(
    const float* __restrict__ A, const float* __restrict__ W,
    const float* __restrict__ bias, float* __restrict__ C,
    int M, int N, int K) {
    __shared__ float As[2][16][128];
    __shared__ float Bs[2][16][128];

    const int tid = threadIdx.x;
    const int n0 = blockIdx.x * 128;
    const int m0 = blockIdx.y * 128;
    const int tx = tid & 15, ty = tid >> 4;

    ull acc2[4][8];
#pragma unroll
    for (int p = 0; p < 4; p++)
#pragma unroll
        for (int j = 0; j < 8; j++) acc2[p][j] = 0ULL;

    const int KT = K >> 4;

#pragma unroll
    for (int i = 0; i < 2; i++) {
        int id = tid * 2 + i, row = id >> 2, kq = id & 3;
        float4 va = *(const float4*)(A + (size_t)(m0 + row) * K + kq * 4);
        float4 vb = *(const float4*)(W + (size_t)(n0 + row) * K + kq * 4);
        As[0][kq * 4 + 0][row] = va.x; As[0][kq * 4 + 1][row] = va.y;
        As[0][kq * 4 + 2][row] = va.z; As[0][kq * 4 + 3][row] = va.w;
        Bs[0][kq * 4 + 0][row] = vb.x; Bs[0][kq * 4 + 1][row] = vb.y;
        Bs[0][kq * 4 + 2][row] = vb.z; Bs[0][kq * 4 + 3][row] = vb.w;
    }
    __syncthreads();

    for (int kt = 0; kt < KT; ++kt) {
        const int cur = kt & 1;
        float4 pa[2], pb[2];
        const bool pf = (kt + 1) < KT;
        if (pf) {
#pragma unroll
            for (int i = 0; i < 2; i++) {
                int id = tid * 2 + i, row = id >> 2, kq = id & 3;
                pa[i] = *(const float4*)(A + (size_t)(m0 + row) * K + (kt + 1) * 16 + kq * 4);
                pb[i] = *(const float4*)(W + (size_t)(n0 + row) * K + (kt + 1) * 16 + kq * 4);
            }
        }
#pragma unroll
        for (int kk = 0; kk < 16; kk++) {
            ulonglong2 a01 = *(const ulonglong2*)&As[cur][kk][ty * 4];
            ulonglong2 a23 = *(const ulonglong2*)&As[cur][kk][64 + ty * 4];
            ull ap[4] = { a01.x, a01.y, a23.x, a23.y };
            float b[8];
            *(float4*)(b)     = *(const float4*)&Bs[cur][kk][tx * 4];
            *(float4*)(b + 4) = *(const float4*)&Bs[cur][kk][64 + tx * 4];
#pragma unroll
            for (int j = 0; j < 8; j++) {
                ull bd = dup2(b[j]);
#pragma unroll
                for (int p = 0; p < 4; p++) ffma2(acc2[p][j], ap[p], bd);
            }
        }
        if (pf) {
            const int nxt = cur ^ 1;
#pragma unroll
            for (int i = 0; i < 2; i++) {
                int id = tid * 2 + i, row = id >> 2, kq = id & 3;
                As[nxt][kq * 4 + 0][row] = pa[i].x; As[nxt][kq * 4 + 1][row] = pa[i].y;
                As[nxt][kq * 4 + 2][row] = pa[i].z; As[nxt][kq * 4 + 3][row] = pa[i].w;
                Bs[nxt][kq * 4 + 0][row] = pb[i].x; Bs[nxt][kq * 4 + 1][row] = pb[i].y;
                Bs[nxt][kq * 4 + 2][row] = pb[i].z; Bs[nxt][kq * 4 + 3][row] = pb[i].w;
            }
        }
        __syncthreads();
    }

    float4 bb0 = *(const float4*)&bias[n0 + tx * 4];
    float4 bb1 = *(const float4*)&bias[n0 + 64 + tx * 4];
#pragma unroll
    for (int p = 0; p < 4; p++) {
        float2 c[8];
#pragma unroll
        for (int j = 0; j < 8; j++) c[j] = unpk2(acc2[p][j]);
#pragma unroll
        for (int half = 0; half < 2; half++) {
            int i = 2 * p + half;
            int m = m0 + ((i < 4) ? (ty * 4 + i) : (64 + ty * 4 + i - 4));
            float e[8];
#pragma unroll
            for (int j = 0; j < 8; j++) e[j] = half ? c[j].y : c[j].x;
            float4 v0 = make_float4(e[0] + bb0.x, e[1] + bb0.y,
                                    e[2] + bb0.z, e[3] + bb0.w);
            float4 v1 = make_float4(e[4] + bb1.x, e[5] + bb1.y,
                                    e[6] + bb1.z, e[7] + bb1.w);
            *(float4*)(C + (size_t)m * N + n0 + tx * 4)      = v0;
            *(float4*)(C + (size_t)m * N + n0 + 64 + tx * 4) = v1;
        }
    }
}

// ---------------- GRU recurrence ---------------------------------------------
// 128 blocks = 4 batch groups (16 rows) x 32 dim groups (16 dims), 512 threads.
// Warp w owns k in [32w, 32w+32); lanes 0-15 take even k, lanes 16-31 odd k.
// Lane (l = lane&15) owns dim l: all 16 rows x 3 gates.
// W_hh lives entirely in REGISTERS (48 floats/lane, loop-invariant): zero W
// smem traffic in the step loop. hsh stride 20 keeps h loads/stores 1-wf.
#define HS 20
#define P4STRIDE 17
#define GRU_SMEM_FLOATS (512 * HS + 16 * 16 * P4STRIDE * 4)
#define GRU_SMEM_BYTES  (GRU_SMEM_FLOATS * 4)

__device__ __forceinline__ unsigned ld_acq(const unsigned* p) {
    unsigned v;
    asm volatile("ld.global.acquire.gpu.u32 %0, [%1];" : "=r"(v) : "l"(p) : "memory");
    return v;
}
__device__ __forceinline__ void st_rel(unsigned* p, unsigned v) {
    asm volatile("st.global.release.gpu.u32 [%0], %1;" :: "l"(p), "r"(v) : "memory");
}

__global__ void __launch_bounds__(512, 1) gru_kernel(
    const float* __restrict__ xg,    // [S][64][1536]
    const float* __restrict__ Whh,   // [1536][512]
    const float* __restrict__ bhh,   // [1536]
    float* __restrict__ ys)          // [S][64][512]
{
    extern __shared__ float sm[];
    float* hsh  = sm;                          // 512*20
    float* part = hsh + 512 * HS;              // 16*16*17*4
    __shared__ unsigned sh_base;

    const int tid = threadIdx.x;
    const int bg  = blockIdx.x & 3;
    const int dg  = blockIdx.x >> 2;
    const int rowBase = bg * 16;
    const int dimBase = dg * 16;

    if (tid == 0) sh_base = *(volatile unsigned*)&g_flags[bg][dg][0];

    // gating role (tid < 256): one thread per (row, dim); h_old in a register
    const int myrow = (tid >> 4) & 15;
    const int mydl  = tid & 15;
    const int mydim = dimBase + mydl;
    float b_r = 0.f, b_z = 0.f, b_n = 0.f;
    float h_old = 0.f;
    if (tid < 256) {
        b_r = bhh[mydim]; b_z = bhh[512 + mydim]; b_n = bhh[1024 + mydim];
    }

    // compute role
    const int w    = tid >> 5;            // warp 0..15, k chunk [32w, 32w+32)
    const int lane = tid & 31;
    const int half = lane >> 4;           // 0: even k, 1: odd k
    const int l    = lane & 15;           // owned dim (local)
    const int k0   = w * 32;

    // W_hh slice -> registers: wreg[it*3+g] = Whh[g*512+dimBase+l][k0+2*it+half]
    float wreg[48];
#pragma unroll
    for (int it = 0; it < 16; ++it) {
        const int k = k0 + 2 * it + half;
#pragma unroll
        for (int g = 0; g < 3; g++)
            wreg[it * 3 + g] = Whh[(size_t)(g * 512 + dimBase + l) * 512 + k];
    }

    __syncthreads();
    const unsigned base = sh_base;

    for (int t = 0; t < S_LEN; ++t) {
        // xg prefetch for gating
        float xr = 0.f, xz = 0.f, xn = 0.f;
        if (tid < 256) {
            size_t xbase = ((size_t)t * 64 + rowBase + myrow) * G3 + mydim;
            xr = xg[xbase]; xz = xg[xbase + 512]; xn = xg[xbase + 1024];
        }

        // ---- warp-private h staging (h stored [k][row], stride 20) ----
        if (t == 0) {
            for (int idx = lane; idx < 32 * HS; idx += 32)
                hsh[k0 * HS + idx] = 0.f;
            __syncwarp();
        } else {
            const unsigned target = base + (unsigned)t;
            const float4* hsrc4 = (const float4*)(ys + ((size_t)(t - 1) * 64 + rowBase) * HID);
            float4 v[2][2];
#pragma unroll
            for (int j = 0; j < 2; j++) {
                const int c = 2 * w + j;   // producer chunk (16 dims = 16 k)
                const unsigned* fp = &g_flags[bg][c][0];
                while ((int)(ld_acq(fp) - target) < 0) { }
#pragma unroll
                for (int i = 0; i < 2; i++) {
                    int idx = i * 32 + lane;
                    int r = idx & 15, fq = idx >> 4;
                    v[j][i] = __ldcg(hsrc4 + (size_t)r * 128 + c * 4 + fq);
                }
            }
#pragma unroll
            for (int j = 0; j < 2; j++) {
                const int c = 2 * w + j;
#pragma unroll
                for (int i = 0; i < 2; i++) {
                    int idx = i * 32 + lane;
                    int r = idx & 15, fq = idx >> 4;
                    int kb = c * 16 + fq * 4;
                    hsh[(kb + 0) * HS + r] = v[j][i].x;
                    hsh[(kb + 1) * HS + r] = v[j][i].y;
                    hsh[(kb + 2) * HS + r] = v[j][i].z;
                    hsh[(kb + 3) * HS + r] = v[j][i].w;
                }
            }
            __syncwarp();
        }

        // ---- GEMM: lane owns dim l, 16 rows (8 row-pairs), 3 gates ----
        ull acc[24];   // [rowpair j][gate g] = acc[j*3+g]
#pragma unroll
        for (int i = 0; i < 24; i++) acc[i] = 0ULL;
#pragma unroll 4
        for (int it = 0; it < 16; ++it) {
            const int k = k0 + 2 * it + half;
            ull wr2 = dup2(wreg[it * 3 + 0]);
            ull wz2 = dup2(wreg[it * 3 + 1]);
            ull wn2 = dup2(wreg[it * 3 + 2]);
            const float* hk = hsh + k * HS;
            ulonglong2 hq[4];
#pragma unroll
            for (int q = 0; q < 4; q++) hq[q] = *(const ulonglong2*)(hk + 4 * q);
            ull hp[8] = { hq[0].x, hq[0].y, hq[1].x, hq[1].y,
                          hq[2].x, hq[2].y, hq[3].x, hq[3].y };
#pragma unroll
            for (int j = 0; j < 8; j++) {
                ffma2(acc[j * 3 + 0], hp[j], wr2);
                ffma2(acc[j * 3 + 1], hp[j], wz2);
                ffma2(acc[j * 3 + 2], hp[j], wn2);
            }
        }

        // ---- merge halves (even k + odd k) ----
#pragma unroll
        for (int i = 0; i < 24; i++) {
            ull o = __shfl_down_sync(0xffffffffu, acc[i], 16);
            acc[i] = add2(acc[i], o);   // lanes<16 hold full 32-k sums
        }

        // ---- write partials (lanes < 16): float4 (r,z,n,0) per row ----
        if (half == 0) {
#pragma unroll
            for (int j = 0; j < 8; j++) {
                float2 r2 = unpk2(acc[j * 3 + 0]);
                float2 z2 = unpk2(acc[j * 3 + 1]);
                float2 n2 = unpk2(acc[j * 3 + 2]);
                float* pp0 = part + (((w * 16 + 2 * j) * P4STRIDE + l) << 2);
                float* pp1 = part + (((w * 16 + 2 * j + 1) * P4STRIDE + l) << 2);
                *(float4*)pp0 = make_float4(r2.x, z2.x, n2.x, 0.f);
                *(float4*)pp1 = make_float4(r2.y, z2.y, n2.y, 0.f);
            }
        }
        __syncthreads();

        // ---- reduce 16 k-groups + gate, one thread per (row, dim) ----
        if (tid < 256) {
            float hr = b_r, hz = b_z, hn = b_n;
#pragma unroll
            for (int kk = 0; kk < 16; kk++) {
                float4 p = *(const float4*)(part +
                    (((kk * 16 + myrow) * P4STRIDE + mydl) << 2));
                hr += p.x; hz += p.y; hn += p.z;
            }
            float er = __expf(-(xr + hr));
            float rr = __fdividef(1.f, 1.f + er);
            float ez = __expf(-(xz + hz));
            float zz = __fdividef(1.f, 1.f + ez);
            float an = xn + rr * hn;
            float e2 = __expf(2.f * an);
            float nn = 1.f - __fdividef(2.f, e2 + 1.f);   // tanh(an)
            float hnew = (1.f - zz) * nn + zz * h_old;
            h_old = hnew;
            ys[((size_t)t * 64 + rowBase + myrow) * HID + mydim] = hnew;
        }

        __syncthreads();
        if (tid == 0) st_rel(&g_flags[bg][dg][0], base + (unsigned)t + 1u);
    }
}

// ---------------- final FC + sigmoid ----------------------------------------
__global__ void fc_kernel(const float* __restrict__ ys,
                          const float* __restrict__ Wfc,
                          const float* __restrict__ bfc,
                          float* __restrict__ out) {
    int b = blockIdx.x, tid = threadIdx.x;
    const float* h = ys + ((size_t)(S_LEN - 1) * 64 + b) * HID;
    float s = 0.f;
    for (int i = tid; i < HID; i += 128) s += h[i] * Wfc[i];
#pragma unroll
    for (int o = 16; o; o >>= 1) s += __shfl_down_sync(0xffffffffu, s, o);
    __shared__ float ps[4];
    if ((tid & 31) == 0) ps[tid >> 5] = s;
    __syncthreads();
    if (tid == 0) {
        float v = ps[0] + ps[1] + ps[2] + ps[3] + bfc[0];
        out[b] = 1.f / (1.f + expf(-v));
    }
}

// ---------------- launch ----------------------------------------------------
extern "C" void kernel_launch(void* const* d_in, const int* in_sizes, int n_in,
                              void* d_out, int out_size) {
    (void)in_sizes; (void)n_in; (void)out_size;
    const int*   x    = (const int*)  d_in[0];
    const float* emb  = (const float*)d_in[1];
    const float* Wih0 = (const float*)d_in[2];
    const float* Whh0 = (const float*)d_in[3];
    const float* bih0 = (const float*)d_in[4];
    const float* bhh0 = (const float*)d_in[5];
    const float* Wih1 = (const float*)d_in[6];
    const float* Whh1 = (const float*)d_in[7];
    const float* bih1 = (const float*)d_in[8];
    const float* bhh1 = (const float*)d_in[9];
    const float* Wfc  = (const float*)d_in[10];
    const float* bfc  = (const float*)d_in[11];
    float* out = (float*)d_out;

    float *xemb, *xgbuf, *ysbuf;
    cudaGetSymbolAddress((void**)&xemb,  g_xemb);
    cudaGetSymbolAddress((void**)&xgbuf, g_xg);
    cudaGetSymbolAddress((void**)&ysbuf, g_ys);

    cudaFuncSetAttribute(gru_kernel, cudaFuncAttributeMaxDynamicSharedMemorySize,
                         GRU_SMEM_BYTES);

    embed_kernel<<<4096, 256>>>(x, emb, xemb);
    gemm_bias_kernel<<<dim3(G3 / 128, M_ROWS / 128), 256>>>(
        xemb, Wih0, bih0, xgbuf, M_ROWS, G3, EMB_D);
    gru_kernel<<<128, 512, GRU_SMEM_BYTES>>>(xgbuf, Whh0, bhh0, ysbuf);
    gemm_bias_kernel<<<dim3(G3 / 128, M_ROWS / 128), 256>>>(
        ysbuf, Wih1, bih1, xgbuf, M_ROWS, G3, HID);
    gru_kernel<<<128, 512, GRU_SMEM_BYTES>>>(xgbuf, Whh1, bhh1, ysbuf);
    fc_kernel<<<64, 128>>>(ysbuf, Wfc, bfc, out);
}